// round 6
// baseline (speedup 1.0000x reference)
#include <cuda_runtime.h>
#include <cstdint>

#define THREADS 256
#define ROWS_PER_BLOCK (THREADS * 2)   // 512

// --- packed f32x2 FMA: two rn-FMAs, one issue slot ---
#define FMA2(d, a, b) asm("fma.rn.f32x2 %0, %1, %2, %0;" : "+l"(d) : "l"(a), "l"(b))
#define PACK2F(d, f)  asm("mov.b64 %0, {%1, %1};" : "=l"(d) : "r"(__float_as_uint(f)))
#define UNPACK2(lo, hi, d) asm("mov.b64 {%0, %1}, %2;" : "=r"(lo), "=r"(hi) : "l"(d))

// --- fast transcendentals on the MUFU pipe ---
__device__ __forceinline__ float softplus_fast(float x) {
    float e, l;
    float y = fabsf(x) * -1.4426950408889634f;
    asm("ex2.approx.f32 %0, %1;" : "=f"(e) : "f"(y));
    float u = 1.0f + e;
    asm("lg2.approx.f32 %0, %1;" : "=f"(l) : "f"(u));
    return fmaxf(x, 0.0f) + l * 0.6931471805599453f;
}
__device__ __forceinline__ float exp_fast(float x) {
    float e;
    asm("ex2.approx.f32 %0, %1;" : "=f"(e) : "f"(x * 1.4426950408889634f));
    return e;
}
__device__ __forceinline__ float rcp_fast(float x) {
    float r;
    asm("rcp.approx.f32 %0, %1;" : "=f"(r) : "f"(x));
    return r;
}

// SMEM layout (floats)
#define SM_WS    0
#define SM_WOUT  9216
#define SM_BOUT  9288
#define SM_X     9296
#define SM_FLOATS (SM_X + ROWS_PER_BLOCK * 27)

// FMA block for one row (acc = ov @ Wk over all 24 j as 12 f32x2 pairs),
// with the OTHER row's softplus/scan-update pairs textually interleaved so
// the MUFU burst hides under FMA/LDS issue (in-order issue requires this).
template <bool DO_SP>
__device__ __forceinline__ void fma_block(
    const float* __restrict__ Wk,
    const float* __restrict__ ov,          // this row's state (read-only here)
    uint64_t* __restrict__ acc,            // this row's 12 fresh accumulators
    uint64_t* __restrict__ oacc,           // other row's finished accumulators
    float* __restrict__ oS,                // other row's running sum S
    float* __restrict__ oov)               // other row's ov (scan update)
{
    #pragma unroll
    for (int p = 0; p < 12; p++) acc[p] = 0ull;

    #pragma unroll
    for (int i = 0; i < 24; i++) {
        const double2* Wr = reinterpret_cast<const double2*>(Wk + i * 24);
        const double2 w0 = Wr[0], w1 = Wr[1], w2 = Wr[2];
        const double2 w3 = Wr[3], w4 = Wr[4], w5 = Wr[5];
        uint64_t wp[12];
        wp[0]  = *reinterpret_cast<const uint64_t*>(&w0.x);
        wp[1]  = *reinterpret_cast<const uint64_t*>(&w0.y);
        wp[2]  = *reinterpret_cast<const uint64_t*>(&w1.x);
        wp[3]  = *reinterpret_cast<const uint64_t*>(&w1.y);
        wp[4]  = *reinterpret_cast<const uint64_t*>(&w2.x);
        wp[5]  = *reinterpret_cast<const uint64_t*>(&w2.y);
        wp[6]  = *reinterpret_cast<const uint64_t*>(&w3.x);
        wp[7]  = *reinterpret_cast<const uint64_t*>(&w3.y);
        wp[8]  = *reinterpret_cast<const uint64_t*>(&w4.x);
        wp[9]  = *reinterpret_cast<const uint64_t*>(&w4.y);
        wp[10] = *reinterpret_cast<const uint64_t*>(&w5.x);
        wp[11] = *reinterpret_cast<const uint64_t*>(&w5.y);

        uint64_t oo;
        PACK2F(oo, ov[i]);
        #pragma unroll
        for (int p = 0; p < 12; p++) FMA2(acc[p], oo, wp[p]);

        if (DO_SP && (i & 1) == 0) {
            const int p  = i >> 1;          // 0..11 over the 24 even i's? i/2 for even i: 0..11
            const int j0 = 2 * p;
            uint32_t lo, hi;
            UNPACK2(lo, hi, oacc[p]);
            oS[j0]     += softplus_fast(__uint_as_float(lo));
            oS[j0 + 1] += softplus_fast(__uint_as_float(hi));
            oov[j0]     -= oS[j0];          // ov_k = ov_{k-1} - S_k (running sum)
            oov[j0 + 1] -= oS[j0 + 1];
        }
    }
}

__device__ __forceinline__ void epilogue_row(
    const float* __restrict__ xr, const float* __restrict__ S,
    const float* __restrict__ sWout, const float* __restrict__ sbout,
    float bt, float bc, float a1, float a2, float a3,
    float* __restrict__ op)
{
    float u[24];
    #pragma unroll
    for (int j = 0; j < 19; j++) u[j] = xr[j] - S[j];
    u[19] = xr[21] - S[19];
    u[20] = xr[24] - S[20];
    u[21] = fmaf(bc, xr[20], fmaf(bt, xr[19], a1)) - S[21];
    u[22] = fmaf(bc, xr[23], fmaf(bt, xr[22], a2)) - S[22];
    u[23] = fmaf(bc, xr[26], fmaf(bt, xr[25], a3)) - S[23];

    float m = u[0];
    #pragma unroll
    for (int j = 1; j < 24; j++) m = fmaxf(m, u[j]);

    float e[24];
    float sum = 0.0f;
    #pragma unroll
    for (int j = 0; j < 24; j++) { e[j] = exp_fast(u[j] - m); sum += e[j]; }
    const float inv = rcp_fast(sum);

    float d0 = 0.0f, d1 = 0.0f, d2 = 0.0f;
    #pragma unroll
    for (int j = 0; j < 24; j++) {
        const float ej = e[j];
        d0 = fmaf(ej, sWout[j * 3 + 0], d0);
        d1 = fmaf(ej, sWout[j * 3 + 1], d1);
        d2 = fmaf(ej, sWout[j * 3 + 2], d2);
    }
    op[0] = fmaxf(fmaf(d0, inv, sbout[0]), 0.0f);
    op[1] = fmaxf(fmaf(d1, inv, sbout[1]), 0.0f);
    op[2] = fmaxf(fmaf(d2, inv, sbout[2]), 0.0f);
}

__global__ __launch_bounds__(THREADS, 1)
void reslogit_kernel(const float* __restrict__ x,
                     const float* __restrict__ asc_train,
                     const float* __restrict__ asc_sm,
                     const float* __restrict__ asc_car,
                     const float* __restrict__ b_time,
                     const float* __restrict__ b_cost,
                     const float* __restrict__ Ws,
                     const float* __restrict__ W_out,
                     const float* __restrict__ b_out,
                     float* __restrict__ out,
                     int B)
{
    extern __shared__ float smem[];
    float* sW    = smem + SM_WS;
    float* sWout = smem + SM_WOUT;
    float* sbout = smem + SM_BOUT;
    float* sx    = smem + SM_X;

    const int tid  = threadIdx.x;
    const int row0 = blockIdx.x * ROWS_PER_BLOCK;

    {
        const float4* Ws4 = reinterpret_cast<const float4*>(Ws);
        float4* sW4 = reinterpret_cast<float4*>(sW);
        #pragma unroll
        for (int i = 0; i < 2304 / THREADS; i++)
            sW4[tid + i * THREADS] = Ws4[tid + i * THREADS];
    }
    if (tid < 72) sWout[tid] = W_out[tid];
    if (tid < 3)  sbout[tid] = b_out[tid];

    {
        const float* xblk = x + (size_t)row0 * 27;
        int nrow  = B - row0; if (nrow > ROWS_PER_BLOCK) nrow = ROWS_PER_BLOCK;
        int nelem = nrow * 27;
        for (int i = tid; i < nelem; i += THREADS) sx[i] = xblk[i];
    }
    __syncthreads();

    const int rowA = row0 + tid;
    const int rowB = rowA + THREADS;
    const bool hasA = rowA < B, hasB = rowB < B;
    if (!hasA) return;

    const float bt = *b_time, bc = *b_cost;
    const float a1 = *asc_train, a2 = *asc_sm, a3 = *asc_car;

    const float* xrA = sx + tid * 27;
    const float* xrB = sx + (tid + THREADS) * 27;

    float ovA[24], ovB[24], SA[24], SB[24];
    #pragma unroll
    for (int j = 0; j < 19; j++) { ovA[j] = xrA[j]; ovB[j] = xrB[j]; }
    ovA[19] = xrA[21]; ovB[19] = xrB[21];
    ovA[20] = xrA[24]; ovB[20] = xrB[24];
    ovA[21] = fmaf(bc, xrA[20], fmaf(bt, xrA[19], a1));
    ovB[21] = fmaf(bc, xrB[20], fmaf(bt, xrB[19], a1));
    ovA[22] = fmaf(bc, xrA[23], fmaf(bt, xrA[22], a2));
    ovB[22] = fmaf(bc, xrB[23], fmaf(bt, xrB[22], a2));
    ovA[23] = fmaf(bc, xrA[26], fmaf(bt, xrA[25], a3));
    ovB[23] = fmaf(bc, xrB[26], fmaf(bt, xrB[25], a3));
    #pragma unroll
    for (int j = 0; j < 24; j++) { SA[j] = 0.0f; SB[j] = 0.0f; }

    uint64_t accA[12], accB[12];

    // Staggered scan: A0, [B0|spA0], [A1|spB0], ..., [B15|spA15], spB15.
    // Every softplus burst is textually embedded inside the other row's FMA
    // i-loop, so in program order the fma pipe never drains during MUFU work.
    fma_block<false>(sW, ovA, accA, accB, SB, ovB);   // A, k=0

    #pragma unroll 1
    for (int k = 0; k < 15; k++) {
        const float* Wk  = sW + k * 576;
        const float* Wk1 = Wk + 576;
        fma_block<true>(Wk,  ovB, accB, accA, SA, ovA);   // B(k)   | sp A(k)
        fma_block<true>(Wk1, ovA, accA, accB, SB, ovB);   // A(k+1) | sp B(k)
    }
    fma_block<true>(sW + 15 * 576, ovB, accB, accA, SA, ovA);  // B(15) | sp A(15)

    // trailing sp for B(15) (only SB needed by the epilogue)
    #pragma unroll
    for (int p = 0; p < 12; p++) {
        uint32_t lo, hi;
        UNPACK2(lo, hi, accB[p]);
        SB[2 * p]     += softplus_fast(__uint_as_float(lo));
        SB[2 * p + 1] += softplus_fast(__uint_as_float(hi));
    }

    epilogue_row(xrA, SA, sWout, sbout, bt, bc, a1, a2, a3, out + (size_t)rowA * 3);
    if (hasB)
        epilogue_row(xrB, SB, sWout, sbout, bt, bc, a1, a2, a3, out + (size_t)rowB * 3);
}

extern "C" void kernel_launch(void* const* d_in, const int* in_sizes, int n_in,
                              void* d_out, int out_size)
{
    const float* x         = (const float*)d_in[0];
    const float* asc_train = (const float*)d_in[1];
    const float* asc_sm    = (const float*)d_in[2];
    const float* asc_car   = (const float*)d_in[3];
    const float* b_time    = (const float*)d_in[4];
    const float* b_cost    = (const float*)d_in[5];
    const float* Ws        = (const float*)d_in[6];
    const float* W_out     = (const float*)d_in[7];
    const float* b_out     = (const float*)d_in[8];
    float* out = (float*)d_out;

    const int B = in_sizes[0] / 27;
    const int smem_bytes = SM_FLOATS * sizeof(float);

    cudaFuncSetAttribute(reslogit_kernel,
                         cudaFuncAttributeMaxDynamicSharedMemorySize, smem_bytes);

    const int grid = (B + ROWS_PER_BLOCK - 1) / ROWS_PER_BLOCK;
    reslogit_kernel<<<grid, THREADS, smem_bytes>>>(
        x, asc_train, asc_sm, asc_car, b_time, b_cost, Ws, W_out, b_out, out, B);
}

// round 7
// speedup vs baseline: 1.1595x; 1.1595x over previous
#include <cuda_runtime.h>
#include <cstdint>

#define THREADS 256
#define ROWS_PER_BLOCK (THREADS * 2)   // 512

// --- packed f32x2 FMA: two rn-FMAs, one issue slot ---
#define FMA2(d, a, b) asm("fma.rn.f32x2 %0, %1, %2, %0;" : "+l"(d) : "l"(a), "l"(b))
#define PACK2F(d, f)  asm("mov.b64 %0, {%1, %1};" : "=l"(d) : "r"(__float_as_uint(f)))
#define UNPACK2(lo, hi, d) asm("mov.b64 {%0, %1}, %2;" : "=r"(lo), "=r"(hi) : "l"(d))

// --- fast transcendentals on the MUFU pipe ---
__device__ __forceinline__ float softplus_fast(float x) {
    float e, l;
    float y = fabsf(x) * -1.4426950408889634f;
    asm("ex2.approx.f32 %0, %1;" : "=f"(e) : "f"(y));
    float u = 1.0f + e;
    asm("lg2.approx.f32 %0, %1;" : "=f"(l) : "f"(u));
    return fmaxf(x, 0.0f) + l * 0.6931471805599453f;
}
__device__ __forceinline__ float exp_fast(float x) {
    float e;
    asm("ex2.approx.f32 %0, %1;" : "=f"(e) : "f"(x * 1.4426950408889634f));
    return e;
}
__device__ __forceinline__ float rcp_fast(float x) {
    float r;
    asm("rcp.approx.f32 %0, %1;" : "=f"(r) : "f"(x));
    return r;
}

// SMEM layout (floats)
#define SM_WS    0
#define SM_WOUT  9216
#define SM_BOUT  9288
#define SM_X     9296
#define SM_FLOATS (SM_X + ROWS_PER_BLOCK * 27)

// softplus + scan update for one packed pair p of one row:
//   S[2p..2p+1] += softplus(acc_p);  ov[2p..2p+1] -= S  (running-sum scan)
__device__ __forceinline__ void sp_pair(uint64_t acc, int j0,
                                        float* __restrict__ S,
                                        float* __restrict__ ov)
{
    uint32_t lo, hi;
    UNPACK2(lo, hi, acc);
    S[j0]     += softplus_fast(__uint_as_float(lo));
    S[j0 + 1] += softplus_fast(__uint_as_float(hi));
    ov[j0]     -= S[j0];
    ov[j0 + 1] -= S[j0 + 1];
}

// One scan step for BOTH rows with shared W loads (one LDS.128 set serves A+B),
// with the PREVIOUS step's softplus pairs interleaved at 2-pair lookahead:
// pair p (p>=2) is processed at iteration i = 2p-4, i.e. ov[2p] is finalized
// well before iteration i=2p consumes it. Pairs 0,1 are handled up front.
template <bool SP>
__device__ __forceinline__ void scan_step(
    const float* __restrict__ Wk,
    float* __restrict__ ovA, float* __restrict__ ovB,
    float* __restrict__ SA,  float* __restrict__ SB,
    uint64_t* __restrict__ newA, uint64_t* __restrict__ newB,   // this step's acc
    const uint64_t* __restrict__ oldA, const uint64_t* __restrict__ oldB) // prev step's acc
{
    if (SP) {   // pairs 0,1 must be final before i=0 reads ov[0..3]
        sp_pair(oldA[0], 0, SA, ovA);
        sp_pair(oldB[0], 0, SB, ovB);
        sp_pair(oldA[1], 2, SA, ovA);
        sp_pair(oldB[1], 2, SB, ovB);
    }

    #pragma unroll
    for (int p = 0; p < 12; p++) { newA[p] = 0ull; newB[p] = 0ull; }

    #pragma unroll
    for (int i = 0; i < 24; i++) {
        // prev-step softplus, 2-pair lookahead: at even i, finalize pair i/2+2
        if (SP && (i & 1) == 0 && (i / 2 + 2) < 12) {
            const int p = i / 2 + 2;
            sp_pair(oldA[p], 2 * p, SA, ovA);
            sp_pair(oldB[p], 2 * p, SB, ovB);
        }

        const double2* Wr = reinterpret_cast<const double2*>(Wk + i * 24);
        const double2 w0 = Wr[0], w1 = Wr[1], w2 = Wr[2];
        const double2 w3 = Wr[3], w4 = Wr[4], w5 = Wr[5];
        uint64_t wp[12];
        wp[0]  = *reinterpret_cast<const uint64_t*>(&w0.x);
        wp[1]  = *reinterpret_cast<const uint64_t*>(&w0.y);
        wp[2]  = *reinterpret_cast<const uint64_t*>(&w1.x);
        wp[3]  = *reinterpret_cast<const uint64_t*>(&w1.y);
        wp[4]  = *reinterpret_cast<const uint64_t*>(&w2.x);
        wp[5]  = *reinterpret_cast<const uint64_t*>(&w2.y);
        wp[6]  = *reinterpret_cast<const uint64_t*>(&w3.x);
        wp[7]  = *reinterpret_cast<const uint64_t*>(&w3.y);
        wp[8]  = *reinterpret_cast<const uint64_t*>(&w4.x);
        wp[9]  = *reinterpret_cast<const uint64_t*>(&w4.y);
        wp[10] = *reinterpret_cast<const uint64_t*>(&w5.x);
        wp[11] = *reinterpret_cast<const uint64_t*>(&w5.y);

        uint64_t ooA, ooB;
        PACK2F(ooA, ovA[i]);
        PACK2F(ooB, ovB[i]);
        #pragma unroll
        for (int p = 0; p < 12; p++) {
            FMA2(newA[p], ooA, wp[p]);
            FMA2(newB[p], ooB, wp[p]);
        }
    }
}

__device__ __forceinline__ void epilogue_row(
    const float* __restrict__ xr, const float* __restrict__ S,
    const float* __restrict__ sWout, const float* __restrict__ sbout,
    float bt, float bc, float a1, float a2, float a3,
    float* __restrict__ op)
{
    float u[24];
    #pragma unroll
    for (int j = 0; j < 19; j++) u[j] = xr[j] - S[j];
    u[19] = xr[21] - S[19];
    u[20] = xr[24] - S[20];
    u[21] = fmaf(bc, xr[20], fmaf(bt, xr[19], a1)) - S[21];
    u[22] = fmaf(bc, xr[23], fmaf(bt, xr[22], a2)) - S[22];
    u[23] = fmaf(bc, xr[26], fmaf(bt, xr[25], a3)) - S[23];

    float m = u[0];
    #pragma unroll
    for (int j = 1; j < 24; j++) m = fmaxf(m, u[j]);

    float e[24];
    float sum = 0.0f;
    #pragma unroll
    for (int j = 0; j < 24; j++) { e[j] = exp_fast(u[j] - m); sum += e[j]; }
    const float inv = rcp_fast(sum);

    float d0 = 0.0f, d1 = 0.0f, d2 = 0.0f;
    #pragma unroll
    for (int j = 0; j < 24; j++) {
        const float ej = e[j];
        d0 = fmaf(ej, sWout[j * 3 + 0], d0);
        d1 = fmaf(ej, sWout[j * 3 + 1], d1);
        d2 = fmaf(ej, sWout[j * 3 + 2], d2);
    }
    op[0] = fmaxf(fmaf(d0, inv, sbout[0]), 0.0f);
    op[1] = fmaxf(fmaf(d1, inv, sbout[1]), 0.0f);
    op[2] = fmaxf(fmaf(d2, inv, sbout[2]), 0.0f);
}

__global__ __launch_bounds__(THREADS, 1)
void reslogit_kernel(const float* __restrict__ x,
                     const float* __restrict__ asc_train,
                     const float* __restrict__ asc_sm,
                     const float* __restrict__ asc_car,
                     const float* __restrict__ b_time,
                     const float* __restrict__ b_cost,
                     const float* __restrict__ Ws,
                     const float* __restrict__ W_out,
                     const float* __restrict__ b_out,
                     float* __restrict__ out,
                     int B)
{
    extern __shared__ float smem[];
    float* sW    = smem + SM_WS;
    float* sWout = smem + SM_WOUT;
    float* sbout = smem + SM_BOUT;
    float* sx    = smem + SM_X;

    const int tid  = threadIdx.x;
    const int row0 = blockIdx.x * ROWS_PER_BLOCK;

    {
        const float4* Ws4 = reinterpret_cast<const float4*>(Ws);
        float4* sW4 = reinterpret_cast<float4*>(sW);
        #pragma unroll
        for (int i = 0; i < 2304 / THREADS; i++)
            sW4[tid + i * THREADS] = Ws4[tid + i * THREADS];
    }
    if (tid < 72) sWout[tid] = W_out[tid];
    if (tid < 3)  sbout[tid] = b_out[tid];

    {
        const float* xblk = x + (size_t)row0 * 27;
        int nrow  = B - row0; if (nrow > ROWS_PER_BLOCK) nrow = ROWS_PER_BLOCK;
        int nelem = nrow * 27;
        for (int i = tid; i < nelem; i += THREADS) sx[i] = xblk[i];
    }
    __syncthreads();

    const int rowA = row0 + tid;
    const int rowB = rowA + THREADS;
    const bool hasA = rowA < B, hasB = rowB < B;
    if (!hasA) return;

    const float bt = *b_time, bc = *b_cost;
    const float a1 = *asc_train, a2 = *asc_sm, a3 = *asc_car;

    const float* xrA = sx + tid * 27;              // stride 27: conflict-free
    const float* xrB = sx + (tid + THREADS) * 27;

    float ovA[24], ovB[24], SA[24], SB[24];
    #pragma unroll
    for (int j = 0; j < 19; j++) { ovA[j] = xrA[j]; ovB[j] = xrB[j]; }
    ovA[19] = xrA[21]; ovB[19] = xrB[21];
    ovA[20] = xrA[24]; ovB[20] = xrB[24];
    ovA[21] = fmaf(bc, xrA[20], fmaf(bt, xrA[19], a1));
    ovB[21] = fmaf(bc, xrB[20], fmaf(bt, xrB[19], a1));
    ovA[22] = fmaf(bc, xrA[23], fmaf(bt, xrA[22], a2));
    ovB[22] = fmaf(bc, xrB[23], fmaf(bt, xrB[22], a2));
    ovA[23] = fmaf(bc, xrA[26], fmaf(bt, xrA[25], a3));
    ovB[23] = fmaf(bc, xrB[26], fmaf(bt, xrB[25], a3));
    #pragma unroll
    for (int j = 0; j < 24; j++) { SA[j] = 0.0f; SB[j] = 0.0f; }

    // Double-buffered accumulators: step k writes P (k even) / Q (k odd);
    // step k+1's FMA loop absorbs step k's softplus with 2-pair lookahead.
    uint64_t accPA[12], accPB[12], accQA[12], accQB[12];

    scan_step<false>(sW, ovA, ovB, SA, SB, accPA, accPB, accQA, accQB);   // k=0 -> P

    #pragma unroll 1
    for (int kk = 0; kk < 7; kk++) {
        const float* Wa = sW + (2 * kk + 1) * 576;   // odd step  -> Q, consumes P
        const float* Wb = Wa + 576;                  // even step -> P, consumes Q
        scan_step<true>(Wa, ovA, ovB, SA, SB, accQA, accQB, accPA, accPB);
        scan_step<true>(Wb, ovA, ovB, SA, SB, accPA, accPB, accQA, accQB);
    }
    scan_step<true>(sW + 15 * 576, ovA, ovB, SA, SB, accQA, accQB, accPA, accPB); // k=15 -> Q

    // tail: softplus of step 15's accumulators (only S needed by epilogue)
    #pragma unroll
    for (int p = 0; p < 12; p++) {
        uint32_t lo, hi;
        UNPACK2(lo, hi, accQA[p]);
        SA[2 * p]     += softplus_fast(__uint_as_float(lo));
        SA[2 * p + 1] += softplus_fast(__uint_as_float(hi));
        UNPACK2(lo, hi, accQB[p]);
        SB[2 * p]     += softplus_fast(__uint_as_float(lo));
        SB[2 * p + 1] += softplus_fast(__uint_as_float(hi));
    }

    epilogue_row(xrA, SA, sWout, sbout, bt, bc, a1, a2, a3, out + (size_t)rowA * 3);
    if (hasB)
        epilogue_row(xrB, SB, sWout, sbout, bt, bc, a1, a2, a3, out + (size_t)rowB * 3);
}

extern "C" void kernel_launch(void* const* d_in, const int* in_sizes, int n_in,
                              void* d_out, int out_size)
{
    const float* x         = (const float*)d_in[0];
    const float* asc_train = (const float*)d_in[1];
    const float* asc_sm    = (const float*)d_in[2];
    const float* asc_car   = (const float*)d_in[3];
    const float* b_time    = (const float*)d_in[4];
    const float* b_cost    = (const float*)d_in[5];
    const float* Ws        = (const float*)d_in[6];
    const float* W_out     = (const float*)d_in[7];
    const float* b_out     = (const float*)d_in[8];
    float* out = (float*)d_out;

    const int B = in_sizes[0] / 27;
    const int smem_bytes = SM_FLOATS * sizeof(float);

    cudaFuncSetAttribute(reslogit_kernel,
                         cudaFuncAttributeMaxDynamicSharedMemorySize, smem_bytes);

    const int grid = (B + ROWS_PER_BLOCK - 1) / ROWS_PER_BLOCK;
    reslogit_kernel<<<grid, THREADS, smem_bytes>>>(
        x, asc_train, asc_sm, asc_car, b_time, b_cost, Ws, W_out, b_out, out, B);
}